// round 16
// baseline (speedup 1.0000x reference)
#include <cuda_runtime.h>
#include <cuda_bf16.h>
#include <cuda_fp16.h>
#include <cstdint>

#define SQ 2048
#define DH 64
#define NBH 24
#define NTILE 16
#define MASKF (-1.0e9f)
#define SCL 0.5f

typedef unsigned long long ull;

// mask dtype flag: 0 = 1-byte bool/uint8, 1 = int32, 2 = float32
__device__ int g_mask_dtype;
// per-(row, 128-col tile) partial softmax stats (m_i, s_i)
__device__ float2 g_MS[(size_t)NBH * SQ * NTILE];
// per-(row, tile) rescale factor f = exp(m_i - M) / S
__device__ float g_F[(size_t)NBH * SQ * NTILE];
// V transposed to [bh][d][k], fp16
__device__ __half g_Vth[(size_t)NBH * DH * SQ];
// unnormalized softmax numerators e = exp(x - m_tile), fp16 (dedicated scratch)
__device__ __half g_E[(size_t)NBH * SQ * SQ];

// ---- cp.async helpers ----
__device__ __forceinline__ void cpasync16(const void* smem_dst, const void* gmem_src) {
    uint32_t d = (uint32_t)__cvta_generic_to_shared(smem_dst);
    asm volatile("cp.async.cg.shared.global [%0], [%1], 16;" :: "r"(d), "l"(gmem_src));
}
__device__ __forceinline__ void cp_commit() { asm volatile("cp.async.commit_group;"); }
__device__ __forceinline__ void cp_wait0()  { asm volatile("cp.async.wait_group 0;"); }

// ---- mma.sync macros ----
#define MMA_BF16(d, a, b0, b1)                                                  \
    asm volatile("mma.sync.aligned.m16n8k16.row.col.f32.bf16.bf16.f32 "         \
                 "{%0,%1,%2,%3}, {%4,%5,%6,%7}, {%8,%9}, {%0,%1,%2,%3};"        \
                 : "+f"((d)[0]), "+f"((d)[1]), "+f"((d)[2]), "+f"((d)[3])       \
                 : "r"((a)[0]), "r"((a)[1]), "r"((a)[2]), "r"((a)[3]),          \
                   "r"(b0), "r"(b1))

#define MMA_F16(d, a, b0, b1)                                                   \
    asm volatile("mma.sync.aligned.m16n8k16.row.col.f32.f16.f16.f32 "           \
                 "{%0,%1,%2,%3}, {%4,%5,%6,%7}, {%8,%9}, {%0,%1,%2,%3};"        \
                 : "+f"((d)[0]), "+f"((d)[1]), "+f"((d)[2]), "+f"((d)[3])       \
                 : "r"((a)[0]), "r"((a)[1]), "r"((a)[2]), "r"((a)[3]),          \
                   "r"(b0), "r"(b1))

__device__ __forceinline__ unsigned pkbf(float a, float b) {
    __nv_bfloat162 v;
    v.x = __float2bfloat16(a);
    v.y = __float2bfloat16(b);
    return *(unsigned*)&v;
}

// =====================================================================
// Kernel 0b: V -> transposed fp16 buffer Vt[d][k].
// Block (0,0) warp 0 additionally detects the mask dtype.
// =====================================================================
__global__ __launch_bounds__(256)
void vconv_kernel(const float* __restrict__ v, const unsigned char* __restrict__ mask) {
    __shared__ float s[64][65];
    const int bh = blockIdx.y;
    const int k0 = blockIdx.x * 64;
    const int t  = threadIdx.x;

    if (blockIdx.x == 0 && blockIdx.y == 0 && t < 32) {
        ull mv = ((const ull*)mask)[t];
        int ge2 = 0, off = 0;
        #pragma unroll
        for (int i = 0; i < 8; ++i) {
            unsigned char b = (unsigned char)((mv >> (8 * i)) & 0xFF);
            const int j = t * 8 + i;
            if (b >= 2) ge2 = 1;
            if ((j & 3) && b) off = 1;
        }
        ge2 = __any_sync(0xFFFFFFFFu, ge2);
        off = __any_sync(0xFFFFFFFFu, off);
        if (t == 0) g_mask_dtype = ge2 ? 2 : (off ? 0 : 1);
    }

    const float* Vg = v + ((size_t)bh * SQ + k0) * DH;
    {
        const int kk = t >> 2, dg = (t & 3) * 16;
        #pragma unroll
        for (int i = 0; i < 4; ++i) {
            float4 x = *(const float4*)(Vg + (size_t)kk * DH + dg + 4 * i);
            s[kk][dg + 4 * i + 0] = x.x; s[kk][dg + 4 * i + 1] = x.y;
            s[kk][dg + 4 * i + 2] = x.z; s[kk][dg + 4 * i + 3] = x.w;
        }
    }
    __syncthreads();
    {
        const int d = t >> 2, kg = (t & 3) * 16;
        __half hi[16];
        #pragma unroll
        for (int i = 0; i < 16; ++i)
            hi[i] = __float2half_rn(s[kg + i][d]);
        const size_t off = ((size_t)bh * DH + d) * SQ + k0 + kg;
        *(uint4*)&g_Vth[off]     = *(uint4*)hi;
        *(uint4*)&g_Vth[off + 8] = *(uint4*)(hi + 8);
    }
}

// =====================================================================
// Kernel 1: tensor-core QK^T via split-bf16 (3 products), fused
// scale+mask+tile-softmax. e-values stored fp16 -> g_E. 128x128, 8 warps.
// (R12 body — known-pass)
// =====================================================================
#define QP 72          // bf16 row pitch
#define QPW 36         // pitch in 32-bit words

__global__ __launch_bounds__(256, 2)
void qk_scores_kernel(const float* __restrict__ q, const float* __restrict__ k,
                      const void* __restrict__ mask) {
    extern __shared__ char smem[];
    __nv_bfloat16* Qh = (__nv_bfloat16*)smem;
    __nv_bfloat16* Ql = Qh + 128 * QP;
    __nv_bfloat16* Kh = Ql + 128 * QP;
    __nv_bfloat16* Kl = Kh + 128 * QP;
    float* Mred = (float*)(smem + 4 * 128 * QP * 2);
    float* Sred = Mred + 256;

    const int t   = threadIdx.x;
    const int bh  = blockIdx.z;
    const int i0  = blockIdx.y * 128;
    const int j0  = blockIdx.x * 128;
    const int wid = t >> 5;
    const int lane = t & 31;
    const int wm  = wid >> 1;
    const int wn  = wid & 1;
    const int g   = lane >> 2;
    const int tig = lane & 3;

    const float* Qg = q + ((size_t)bh * SQ + i0) * DH;
    const float* Kg = k + ((size_t)bh * SQ + j0) * DH;

    #pragma unroll
    for (int i = 0; i < 8; ++i) {
        const int id  = t + 256 * i;
        const int row = id >> 4;
        const int c   = (id & 15) * 4;
        float4 x = *(const float4*)(Qg + row * DH + c);
        float h0 = __bfloat162float(__float2bfloat16(x.x));
        float h1 = __bfloat162float(__float2bfloat16(x.y));
        float h2 = __bfloat162float(__float2bfloat16(x.z));
        float h3 = __bfloat162float(__float2bfloat16(x.w));
        *(uint2*)&Qh[row * QP + c] = make_uint2(pkbf(h0, h1), pkbf(h2, h3));
        *(uint2*)&Ql[row * QP + c] =
            make_uint2(pkbf(x.x - h0, x.y - h1), pkbf(x.z - h2, x.w - h3));
        float4 y = *(const float4*)(Kg + row * DH + c);
        float k0 = __bfloat162float(__float2bfloat16(y.x));
        float k1 = __bfloat162float(__float2bfloat16(y.y));
        float k2 = __bfloat162float(__float2bfloat16(y.z));
        float k3 = __bfloat162float(__float2bfloat16(y.w));
        *(uint2*)&Kh[row * QP + c] = make_uint2(pkbf(k0, k1), pkbf(k2, k3));
        *(uint2*)&Kl[row * QP + c] =
            make_uint2(pkbf(y.x - k0, y.y - k1), pkbf(y.z - k2, y.w - k3));
    }
    __syncthreads();

    const unsigned* Qhu = (const unsigned*)Qh;
    const unsigned* Qlu = (const unsigned*)Ql;
    const unsigned* Khu = (const unsigned*)Kh;
    const unsigned* Klu = (const unsigned*)Kl;

    float acc[2][8][4];
    #pragma unroll
    for (int a = 0; a < 2; ++a)
        #pragma unroll
        for (int b = 0; b < 8; ++b)
            #pragma unroll
            for (int c = 0; c < 4; ++c) acc[a][b][c] = 0.0f;

    #pragma unroll
    for (int ks = 0; ks < 4; ++ks) {
        unsigned aH[2][4], aL[2][4];
        #pragma unroll
        for (int mi = 0; mi < 2; ++mi) {
            const int w = (wm * 32 + mi * 16 + g) * QPW + 8 * ks + tig;
            aH[mi][0] = Qhu[w];       aH[mi][1] = Qhu[w + 8 * QPW];
            aH[mi][2] = Qhu[w + 4];   aH[mi][3] = Qhu[w + 8 * QPW + 4];
            aL[mi][0] = Qlu[w];       aL[mi][1] = Qlu[w + 8 * QPW];
            aL[mi][2] = Qlu[w + 4];   aL[mi][3] = Qlu[w + 8 * QPW + 4];
        }
        #pragma unroll
        for (int ni = 0; ni < 8; ++ni) {
            const int wb = (wn * 64 + ni * 8 + g) * QPW + 8 * ks + tig;
            const unsigned bh0 = Khu[wb], bh1 = Khu[wb + 4];
            const unsigned bl0 = Klu[wb], bl1 = Klu[wb + 4];
            MMA_BF16(acc[0][ni], aH[0], bh0, bh1);
            MMA_BF16(acc[1][ni], aH[1], bh0, bh1);
            MMA_BF16(acc[0][ni], aL[0], bh0, bh1);
            MMA_BF16(acc[1][ni], aL[1], bh0, bh1);
            MMA_BF16(acc[0][ni], aH[0], bl0, bl1);
            MMA_BF16(acc[1][ni], aH[1], bl0, bl1);
        }
    }
    __syncthreads();

    const int mf = g_mask_dtype;

    #pragma unroll
    for (int mi = 0; mi < 2; ++mi) {
        #pragma unroll
        for (int h = 0; h < 2; ++h) {
            const int row_l = wm * 32 + mi * 16 + h * 8 + g;
            const int grow  = i0 + row_l;
            float mm = -3.0e38f;
            #pragma unroll
            for (int ni = 0; ni < 8; ++ni) {
                float& x0 = acc[mi][ni][2 * h];
                float& x1 = acc[mi][ni][2 * h + 1];
                x0 *= SCL; x1 *= SCL;
                const size_t idx =
                    ((size_t)bh * SQ + grow) * SQ + j0 + wn * 64 + ni * 8 + 2 * tig;
                if (mf == 0) {
                    uchar2 m = *(const uchar2*)((const unsigned char*)mask + idx);
                    if (m.x) x0 = MASKF; if (m.y) x1 = MASKF;
                } else if (mf == 1) {
                    int2 m = *(const int2*)((const int*)mask + idx);
                    if (m.x) x0 = MASKF; if (m.y) x1 = MASKF;
                } else {
                    float2 m = *(const float2*)((const float*)mask + idx);
                    if (m.x != 0.0f) x0 = MASKF; if (m.y != 0.0f) x1 = MASKF;
                }
                mm = fmaxf(mm, fmaxf(x0, x1));
            }
            mm = fmaxf(mm, __shfl_xor_sync(0xFFFFFFFFu, mm, 1));
            mm = fmaxf(mm, __shfl_xor_sync(0xFFFFFFFFu, mm, 2));
            Mred[row_l * 2 + wn] = mm;
        }
    }
    __syncthreads();

    #pragma unroll
    for (int mi = 0; mi < 2; ++mi) {
        #pragma unroll
        for (int h = 0; h < 2; ++h) {
            const int row_l = wm * 32 + mi * 16 + h * 8 + g;
            const int grow  = i0 + row_l;
            const float m = fmaxf(Mred[row_l * 2], Mred[row_l * 2 + 1]);
            float s = 0.0f;
            #pragma unroll
            for (int ni = 0; ni < 8; ++ni) {
                const float e0 = __expf(acc[mi][ni][2 * h]     - m);
                const float e1 = __expf(acc[mi][ni][2 * h + 1] - m);
                s += e0 + e1;
                const size_t idx =
                    ((size_t)bh * SQ + grow) * SQ + j0 + wn * 64 + ni * 8 + 2 * tig;
                *(__half2*)(g_E + idx) = __float22half2_rn(make_float2(e0, e1));
            }
            s += __shfl_xor_sync(0xFFFFFFFFu, s, 1);
            s += __shfl_xor_sync(0xFFFFFFFFu, s, 2);
            Sred[row_l * 2 + wn] = s;
        }
    }
    __syncthreads();

    if (wn == 0 && tig == 0) {
        #pragma unroll
        for (int mi = 0; mi < 2; ++mi)
            #pragma unroll
            for (int h = 0; h < 2; ++h) {
                const int row_l = wm * 32 + mi * 16 + h * 8 + g;
                const int grow  = i0 + row_l;
                const float m = fmaxf(Mred[row_l * 2], Mred[row_l * 2 + 1]);
                const float S = Sred[row_l * 2] + Sred[row_l * 2 + 1];
                g_MS[((size_t)bh * SQ + grow) * NTILE + blockIdx.x] =
                    make_float2(m, S);
            }
    }
}

// =====================================================================
// Kernel 2: combine per-tile stats -> per-(row, tile) factor f
// =====================================================================
__global__ __launch_bounds__(128)
void combine_kernel() {
    const size_t row = (size_t)blockIdx.x * 128 + threadIdx.x;
    const float4* mp = (const float4*)(g_MS + row * NTILE);
    float4 r[8];
    #pragma unroll
    for (int i = 0; i < 8; ++i) r[i] = mp[i];
    float M = r[0].x;
    #pragma unroll
    for (int i = 0; i < 8; ++i) { M = fmaxf(M, r[i].x); M = fmaxf(M, r[i].z); }
    float e[16], S = 0.0f;
    #pragma unroll
    for (int i = 0; i < 8; ++i) {
        e[2 * i]     = __expf(r[i].x - M); S += r[i].y * e[2 * i];
        e[2 * i + 1] = __expf(r[i].z - M); S += r[i].w * e[2 * i + 1];
    }
    const float inv = 1.0f / S;
    float4* f = (float4*)(g_F + row * NTILE);
    #pragma unroll
    for (int i = 0; i < 4; ++i)
        f[i] = make_float4(e[4 * i] * inv, e[4 * i + 1] * inv,
                           e[4 * i + 2] * inv, e[4 * i + 3] * inv);
}

// =====================================================================
// Kernel 3: context = attn @ V via fp16 tensor cores. 64-row tiles
// (grid 768 CTAs -> 86% wave fill vs 65% at 128 rows). 8 warps: 2m x 4n.
// Writes normalized fp32 attn + fp32 ctx. Arithmetic identical to R12.
// =====================================================================
#define AVP 72
#define AVPW 36
#define AV_BK 64
#define AV_MT 64       // row-tile

__global__ __launch_bounds__(256, 2)
void av_kernel(float* __restrict__ attn, float* __restrict__ ctx) {
    extern __shared__ char smem[];
    __half* base = (__half*)smem;
    __half* As[2]  = { base, base + AV_MT * AVP };
    __half* vb = base + 2 * AV_MT * AVP;
    __half* VsH[2] = { vb, vb + 64 * AVP };

    const int t   = threadIdx.x;
    const int bh  = blockIdx.y;
    const int i0  = blockIdx.x * AV_MT;
    const int wid = t >> 5;
    const int lane = t & 31;
    const int wm  = wid >> 2;        // 0..1 : rows wm*32..+31
    const int wn  = wid & 3;         // 0..3 : cols wn*16..+15
    const int g   = lane >> 2;
    const int tig = lane & 3;

    const __half* Eg = g_E + ((size_t)bh * SQ + i0) * SQ;
    float* Ag32 = attn + ((size_t)bh * SQ + i0) * SQ;
    const __half* Vth = g_Vth + (size_t)bh * DH * SQ;

    const int rg = (t >> 3) * 2;     // rows rg..rg+1
    const int kg = (t & 7) * 8;      // k cols kg..kg+7

    uint4 ra[2];
    float fv[2];

    float acc[2][2][4];
    #pragma unroll
    for (int a = 0; a < 2; ++a)
        #pragma unroll
        for (int b = 0; b < 2; ++b)
            #pragma unroll
            for (int c = 0; c < 4; ++c) acc[a][b][c] = 0.0f;

    auto ldF = [&](int kt) {
        #pragma unroll
        for (int i = 0; i < 2; ++i)
            fv[i] = g_F[((size_t)bh * SQ + i0 + rg + i) * NTILE + kt];
    };
    auto ldA = [&](int n) {
        #pragma unroll
        for (int i = 0; i < 2; ++i)
            ra[i] = *(const uint4*)(Eg + (size_t)(rg + i) * SQ + n * AV_BK + kg);
    };
    auto ldV = [&](int n, int buf) {
        #pragma unroll
        for (int it = 0; it < 2; ++it) {
            const int id  = it * 256 + t;
            const int d   = id >> 3;
            const int seg = (id & 7) * 8;
            cpasync16(VsH[buf] + d * AVP + seg, Vth + (size_t)d * SQ + n * AV_BK + seg);
        }
        cp_commit();
    };
    auto procA = [&](int n, int buf) {
        #pragma unroll
        for (int i = 0; i < 2; ++i) {
            const int row = rg + i;
            const float f = fv[i];
            const __half2* hp = (const __half2*)&ra[i];
            float2 p0 = __half22float2(hp[0]);
            float2 p1 = __half22float2(hp[1]);
            float2 p2 = __half22float2(hp[2]);
            float2 p3 = __half22float2(hp[3]);
            p0.x *= f; p0.y *= f; p1.x *= f; p1.y *= f;
            p2.x *= f; p2.y *= f; p3.x *= f; p3.y *= f;
            float* p = Ag32 + (size_t)row * SQ + n * AV_BK + kg;
            *(float4*)p       = make_float4(p0.x, p0.y, p1.x, p1.y);
            *(float4*)(p + 4) = make_float4(p2.x, p2.y, p3.x, p3.y);
            uint4 w;
            *(__half2*)&w.x = __float22half2_rn(p0);
            *(__half2*)&w.y = __float22half2_rn(p1);
            *(__half2*)&w.z = __float22half2_rn(p2);
            *(__half2*)&w.w = __float22half2_rn(p3);
            *(uint4*)&As[buf][row * AVP + kg] = w;
        }
    };

    ldF(0);
    ldA(0);
    ldV(0, 0);
    procA(0, 0);
    cp_wait0();
    __syncthreads();

    for (int c = 0; c < SQ / AV_BK; ++c) {
        const int cur = c & 1;
        if (c < SQ / AV_BK - 1) {
            const int n = c + 1;
            if ((n & 1) == 0) ldF(n >> 1);
            ldA(n);
            ldV(n, 1 - cur);
        }
        {
            const unsigned* A  = (const unsigned*)As[cur];
            const unsigned* VH = (const unsigned*)VsH[cur];
            #pragma unroll
            for (int ks = 0; ks < 4; ++ks) {
                unsigned a[2][4];
                #pragma unroll
                for (int mi = 0; mi < 2; ++mi) {
                    const int w = (wm * 32 + mi * 16 + g) * AVPW + 8 * ks + tig;
                    a[mi][0] = A[w];       a[mi][1] = A[w + 8 * AVPW];
                    a[mi][2] = A[w + 4];   a[mi][3] = A[w + 8 * AVPW + 4];
                }
                #pragma unroll
                for (int ni = 0; ni < 2; ++ni) {
                    const int wb = (wn * 16 + ni * 8 + g) * AVPW + 8 * ks + tig;
                    const unsigned bh0 = VH[wb], bh1 = VH[wb + 4];
                    MMA_F16(acc[0][ni], a[0], bh0, bh1);
                    MMA_F16(acc[1][ni], a[1], bh0, bh1);
                }
            }
        }
        if (c < SQ / AV_BK - 1) {
            procA(c + 1, 1 - cur);
            cp_wait0();
        }
        __syncthreads();
    }

    #pragma unroll
    for (int mi = 0; mi < 2; ++mi)
        #pragma unroll
        for (int ni = 0; ni < 2; ++ni)
            #pragma unroll
            for (int h = 0; h < 2; ++h) {
                const int row = i0 + wm * 32 + mi * 16 + h * 8 + g;
                const int col = wn * 16 + ni * 8 + 2 * tig;
                *(float2*)(ctx + ((size_t)bh * SQ + row) * DH + col) =
                    make_float2(acc[mi][ni][2 * h], acc[mi][ni][2 * h + 1]);
            }
}

// =====================================================================
extern "C" void kernel_launch(void* const* d_in, const int* in_sizes, int n_in,
                              void* d_out, int out_size) {
    const float* q = (const float*)d_in[0];
    const float* k = (const float*)d_in[1];
    const float* v = (const float*)d_in[2];
    const void*  mask = d_in[3];

    float* ctx  = (float*)d_out;                              // [24, 2048, 64]
    float* attn = (float*)d_out + (size_t)NBH * SQ * DH;      // [24, 2048, 2048]

    const int qk_smem = 4 * 128 * QP * 2 + 512 * 4;           // 75776
    cudaFuncSetAttribute(qk_scores_kernel,
                         cudaFuncAttributeMaxDynamicSharedMemorySize, qk_smem);
    const int av_smem = (2 * AV_MT * AVP + 2 * 64 * AVP) * 2; // 36864
    cudaFuncSetAttribute(av_kernel,
                         cudaFuncAttributeMaxDynamicSharedMemorySize, av_smem);

    dim3 gv(SQ / 64, NBH);
    vconv_kernel<<<gv, 256>>>(v, (const unsigned char*)mask);

    dim3 g1(SQ / 128, SQ / 128, NBH);
    qk_scores_kernel<<<g1, 256, qk_smem>>>(q, k, mask);

    combine_kernel<<<NBH * SQ / 128, 128>>>();

    dim3 g3(SQ / AV_MT, NBH);
    av_kernel<<<g3, 256, av_smem>>>(attn, ctx);
}

// round 17
// speedup vs baseline: 1.1206x; 1.1206x over previous
#include <cuda_runtime.h>
#include <cuda_bf16.h>
#include <cuda_fp16.h>
#include <cstdint>

#define SQ 2048
#define DH 64
#define NBH 24
#define NTILE 16
#define MASKF (-1.0e9f)
#define SCL 0.5f

typedef unsigned long long ull;

// mask dtype flag: 0 = 1-byte bool/uint8, 1 = int32, 2 = float32
__device__ int g_mask_dtype;
// per-(row, 128-col tile) partial softmax stats (m_i, s_i)
__device__ float2 g_MS[(size_t)NBH * SQ * NTILE];
// per-(row, tile) rescale factor f = exp(m_i - M) / S
__device__ float g_F[(size_t)NBH * SQ * NTILE];
// V transposed to [bh][d][k], fp16
__device__ __half g_Vth[(size_t)NBH * DH * SQ];
// unnormalized softmax numerators e = exp(x - m_tile), fp16 (dedicated scratch)
__device__ __half g_E[(size_t)NBH * SQ * SQ];

// ---- cp.async helpers ----
__device__ __forceinline__ void cpasync16(const void* smem_dst, const void* gmem_src) {
    uint32_t d = (uint32_t)__cvta_generic_to_shared(smem_dst);
    asm volatile("cp.async.cg.shared.global [%0], [%1], 16;" :: "r"(d), "l"(gmem_src));
}
__device__ __forceinline__ void cp_commit() { asm volatile("cp.async.commit_group;"); }
__device__ __forceinline__ void cp_wait0()  { asm volatile("cp.async.wait_group 0;"); }

// ---- mma.sync macros ----
#define MMA_BF16(d, a, b0, b1)                                                  \
    asm volatile("mma.sync.aligned.m16n8k16.row.col.f32.bf16.bf16.f32 "         \
                 "{%0,%1,%2,%3}, {%4,%5,%6,%7}, {%8,%9}, {%0,%1,%2,%3};"        \
                 : "+f"((d)[0]), "+f"((d)[1]), "+f"((d)[2]), "+f"((d)[3])       \
                 : "r"((a)[0]), "r"((a)[1]), "r"((a)[2]), "r"((a)[3]),          \
                   "r"(b0), "r"(b1))

#define MMA_F16(d, a, b0, b1)                                                   \
    asm volatile("mma.sync.aligned.m16n8k16.row.col.f32.f16.f16.f32 "           \
                 "{%0,%1,%2,%3}, {%4,%5,%6,%7}, {%8,%9}, {%0,%1,%2,%3};"        \
                 : "+f"((d)[0]), "+f"((d)[1]), "+f"((d)[2]), "+f"((d)[3])       \
                 : "r"((a)[0]), "r"((a)[1]), "r"((a)[2]), "r"((a)[3]),          \
                   "r"(b0), "r"(b1))

__device__ __forceinline__ unsigned pkbf(float a, float b) {
    __nv_bfloat162 v;
    v.x = __float2bfloat16(a);
    v.y = __float2bfloat16(b);
    return *(unsigned*)&v;
}

// =====================================================================
// Kernel 0b: V -> transposed fp16 buffer Vt[d][k].
// Block (0,0) warp 0 additionally detects the mask dtype.
// =====================================================================
__global__ __launch_bounds__(256)
void vconv_kernel(const float* __restrict__ v, const unsigned char* __restrict__ mask) {
    __shared__ float s[64][65];
    const int bh = blockIdx.y;
    const int k0 = blockIdx.x * 64;
    const int t  = threadIdx.x;

    if (blockIdx.x == 0 && blockIdx.y == 0 && t < 32) {
        ull mv = ((const ull*)mask)[t];
        int ge2 = 0, off = 0;
        #pragma unroll
        for (int i = 0; i < 8; ++i) {
            unsigned char b = (unsigned char)((mv >> (8 * i)) & 0xFF);
            const int j = t * 8 + i;
            if (b >= 2) ge2 = 1;
            if ((j & 3) && b) off = 1;
        }
        ge2 = __any_sync(0xFFFFFFFFu, ge2);
        off = __any_sync(0xFFFFFFFFu, off);
        if (t == 0) g_mask_dtype = ge2 ? 2 : (off ? 0 : 1);
    }

    const float* Vg = v + ((size_t)bh * SQ + k0) * DH;
    {
        const int kk = t >> 2, dg = (t & 3) * 16;
        #pragma unroll
        for (int i = 0; i < 4; ++i) {
            float4 x = *(const float4*)(Vg + (size_t)kk * DH + dg + 4 * i);
            s[kk][dg + 4 * i + 0] = x.x; s[kk][dg + 4 * i + 1] = x.y;
            s[kk][dg + 4 * i + 2] = x.z; s[kk][dg + 4 * i + 3] = x.w;
        }
    }
    __syncthreads();
    {
        const int d = t >> 2, kg = (t & 3) * 16;
        __half hi[16];
        #pragma unroll
        for (int i = 0; i < 16; ++i)
            hi[i] = __float2half_rn(s[kg + i][d]);
        const size_t off = ((size_t)bh * DH + d) * SQ + k0 + kg;
        *(uint4*)&g_Vth[off]     = *(uint4*)hi;
        *(uint4*)&g_Vth[off + 8] = *(uint4*)(hi + 8);
    }
}

// =====================================================================
// Kernel 1: tensor-core QK^T via split-bf16 (3 products), fused
// scale+mask+tile-softmax. e-values stored fp16 -> g_E. 128x128, 8 warps.
// (R12 body — known-pass)
// =====================================================================
#define QP 72          // bf16 row pitch
#define QPW 36         // pitch in 32-bit words

__global__ __launch_bounds__(256, 2)
void qk_scores_kernel(const float* __restrict__ q, const float* __restrict__ k,
                      const void* __restrict__ mask) {
    extern __shared__ char smem[];
    __nv_bfloat16* Qh = (__nv_bfloat16*)smem;
    __nv_bfloat16* Ql = Qh + 128 * QP;
    __nv_bfloat16* Kh = Ql + 128 * QP;
    __nv_bfloat16* Kl = Kh + 128 * QP;
    float* Mred = (float*)(smem + 4 * 128 * QP * 2);
    float* Sred = Mred + 256;

    const int t   = threadIdx.x;
    const int bh  = blockIdx.z;
    const int i0  = blockIdx.y * 128;
    const int j0  = blockIdx.x * 128;
    const int wid = t >> 5;
    const int lane = t & 31;
    const int wm  = wid >> 1;
    const int wn  = wid & 1;
    const int g   = lane >> 2;
    const int tig = lane & 3;

    const float* Qg = q + ((size_t)bh * SQ + i0) * DH;
    const float* Kg = k + ((size_t)bh * SQ + j0) * DH;

    #pragma unroll
    for (int i = 0; i < 8; ++i) {
        const int id  = t + 256 * i;
        const int row = id >> 4;
        const int c   = (id & 15) * 4;
        float4 x = *(const float4*)(Qg + row * DH + c);
        float h0 = __bfloat162float(__float2bfloat16(x.x));
        float h1 = __bfloat162float(__float2bfloat16(x.y));
        float h2 = __bfloat162float(__float2bfloat16(x.z));
        float h3 = __bfloat162float(__float2bfloat16(x.w));
        *(uint2*)&Qh[row * QP + c] = make_uint2(pkbf(h0, h1), pkbf(h2, h3));
        *(uint2*)&Ql[row * QP + c] =
            make_uint2(pkbf(x.x - h0, x.y - h1), pkbf(x.z - h2, x.w - h3));
        float4 y = *(const float4*)(Kg + row * DH + c);
        float k0 = __bfloat162float(__float2bfloat16(y.x));
        float k1 = __bfloat162float(__float2bfloat16(y.y));
        float k2 = __bfloat162float(__float2bfloat16(y.z));
        float k3 = __bfloat162float(__float2bfloat16(y.w));
        *(uint2*)&Kh[row * QP + c] = make_uint2(pkbf(k0, k1), pkbf(k2, k3));
        *(uint2*)&Kl[row * QP + c] =
            make_uint2(pkbf(y.x - k0, y.y - k1), pkbf(y.z - k2, y.w - k3));
    }
    __syncthreads();

    const unsigned* Qhu = (const unsigned*)Qh;
    const unsigned* Qlu = (const unsigned*)Ql;
    const unsigned* Khu = (const unsigned*)Kh;
    const unsigned* Klu = (const unsigned*)Kl;

    float acc[2][8][4];
    #pragma unroll
    for (int a = 0; a < 2; ++a)
        #pragma unroll
        for (int b = 0; b < 8; ++b)
            #pragma unroll
            for (int c = 0; c < 4; ++c) acc[a][b][c] = 0.0f;

    #pragma unroll
    for (int ks = 0; ks < 4; ++ks) {
        unsigned aH[2][4], aL[2][4];
        #pragma unroll
        for (int mi = 0; mi < 2; ++mi) {
            const int w = (wm * 32 + mi * 16 + g) * QPW + 8 * ks + tig;
            aH[mi][0] = Qhu[w];       aH[mi][1] = Qhu[w + 8 * QPW];
            aH[mi][2] = Qhu[w + 4];   aH[mi][3] = Qhu[w + 8 * QPW + 4];
            aL[mi][0] = Qlu[w];       aL[mi][1] = Qlu[w + 8 * QPW];
            aL[mi][2] = Qlu[w + 4];   aL[mi][3] = Qlu[w + 8 * QPW + 4];
        }
        #pragma unroll
        for (int ni = 0; ni < 8; ++ni) {
            const int wb = (wn * 64 + ni * 8 + g) * QPW + 8 * ks + tig;
            const unsigned bh0 = Khu[wb], bh1 = Khu[wb + 4];
            const unsigned bl0 = Klu[wb], bl1 = Klu[wb + 4];
            MMA_BF16(acc[0][ni], aH[0], bh0, bh1);
            MMA_BF16(acc[1][ni], aH[1], bh0, bh1);
            MMA_BF16(acc[0][ni], aL[0], bh0, bh1);
            MMA_BF16(acc[1][ni], aL[1], bh0, bh1);
            MMA_BF16(acc[0][ni], aH[0], bl0, bl1);
            MMA_BF16(acc[1][ni], aH[1], bl0, bl1);
        }
    }
    __syncthreads();

    const int mf = g_mask_dtype;

    #pragma unroll
    for (int mi = 0; mi < 2; ++mi) {
        #pragma unroll
        for (int h = 0; h < 2; ++h) {
            const int row_l = wm * 32 + mi * 16 + h * 8 + g;
            const int grow  = i0 + row_l;
            float mm = -3.0e38f;
            #pragma unroll
            for (int ni = 0; ni < 8; ++ni) {
                float& x0 = acc[mi][ni][2 * h];
                float& x1 = acc[mi][ni][2 * h + 1];
                x0 *= SCL; x1 *= SCL;
                const size_t idx =
                    ((size_t)bh * SQ + grow) * SQ + j0 + wn * 64 + ni * 8 + 2 * tig;
                if (mf == 0) {
                    uchar2 m = *(const uchar2*)((const unsigned char*)mask + idx);
                    if (m.x) x0 = MASKF; if (m.y) x1 = MASKF;
                } else if (mf == 1) {
                    int2 m = *(const int2*)((const int*)mask + idx);
                    if (m.x) x0 = MASKF; if (m.y) x1 = MASKF;
                } else {
                    float2 m = *(const float2*)((const float*)mask + idx);
                    if (m.x != 0.0f) x0 = MASKF; if (m.y != 0.0f) x1 = MASKF;
                }
                mm = fmaxf(mm, fmaxf(x0, x1));
            }
            mm = fmaxf(mm, __shfl_xor_sync(0xFFFFFFFFu, mm, 1));
            mm = fmaxf(mm, __shfl_xor_sync(0xFFFFFFFFu, mm, 2));
            Mred[row_l * 2 + wn] = mm;
        }
    }
    __syncthreads();

    #pragma unroll
    for (int mi = 0; mi < 2; ++mi) {
        #pragma unroll
        for (int h = 0; h < 2; ++h) {
            const int row_l = wm * 32 + mi * 16 + h * 8 + g;
            const int grow  = i0 + row_l;
            const float m = fmaxf(Mred[row_l * 2], Mred[row_l * 2 + 1]);
            float s = 0.0f;
            #pragma unroll
            for (int ni = 0; ni < 8; ++ni) {
                const float e0 = __expf(acc[mi][ni][2 * h]     - m);
                const float e1 = __expf(acc[mi][ni][2 * h + 1] - m);
                s += e0 + e1;
                const size_t idx =
                    ((size_t)bh * SQ + grow) * SQ + j0 + wn * 64 + ni * 8 + 2 * tig;
                *(__half2*)(g_E + idx) = __float22half2_rn(make_float2(e0, e1));
            }
            s += __shfl_xor_sync(0xFFFFFFFFu, s, 1);
            s += __shfl_xor_sync(0xFFFFFFFFu, s, 2);
            Sred[row_l * 2 + wn] = s;
        }
    }
    __syncthreads();

    if (wn == 0 && tig == 0) {
        #pragma unroll
        for (int mi = 0; mi < 2; ++mi)
            #pragma unroll
            for (int h = 0; h < 2; ++h) {
                const int row_l = wm * 32 + mi * 16 + h * 8 + g;
                const int grow  = i0 + row_l;
                const float m = fmaxf(Mred[row_l * 2], Mred[row_l * 2 + 1]);
                const float S = Sred[row_l * 2] + Sred[row_l * 2 + 1];
                g_MS[((size_t)bh * SQ + grow) * NTILE + blockIdx.x] =
                    make_float2(m, S);
            }
    }
}

// =====================================================================
// Kernel 2: combine per-tile stats -> per-(row, tile) factor f
// =====================================================================
__global__ __launch_bounds__(128)
void combine_kernel() {
    const size_t row = (size_t)blockIdx.x * 128 + threadIdx.x;
    const float4* mp = (const float4*)(g_MS + row * NTILE);
    float4 r[8];
    #pragma unroll
    for (int i = 0; i < 8; ++i) r[i] = mp[i];
    float M = r[0].x;
    #pragma unroll
    for (int i = 0; i < 8; ++i) { M = fmaxf(M, r[i].x); M = fmaxf(M, r[i].z); }
    float e[16], S = 0.0f;
    #pragma unroll
    for (int i = 0; i < 8; ++i) {
        e[2 * i]     = __expf(r[i].x - M); S += r[i].y * e[2 * i];
        e[2 * i + 1] = __expf(r[i].z - M); S += r[i].w * e[2 * i + 1];
    }
    const float inv = 1.0f / S;
    float4* f = (float4*)(g_F + row * NTILE);
    #pragma unroll
    for (int i = 0; i < 4; ++i)
        f[i] = make_float4(e[4 * i] * inv, e[4 * i + 1] * inv,
                           e[4 * i + 2] * inv, e[4 * i + 3] * inv);
}

// =====================================================================
// Kernel 3: context = attn @ V via fp16 tensor cores (A fp16 from g_E,
// V fp16 single product). Writes normalized fp32 attn + fp32 ctx.
// R12 body, but __launch_bounds__(256,3): cap 85 regs -> 3 CTAs/SM.
// =====================================================================
#define AVP 72
#define AVPW 36
#define AV_BK 64

__global__ __launch_bounds__(256, 3)
void av_kernel(float* __restrict__ attn, float* __restrict__ ctx) {
    extern __shared__ char smem[];
    __half* base = (__half*)smem;
    __half* As[2]  = { base, base + 128 * AVP };
    __half* vb = base + 2 * 128 * AVP;
    __half* VsH[2] = { vb, vb + 64 * AVP };

    const int t   = threadIdx.x;
    const int bh  = blockIdx.y;
    const int i0  = blockIdx.x * 128;
    const int wid = t >> 5;
    const int lane = t & 31;
    const int wm  = wid >> 1;        // rows wm*32..+31
    const int wn  = wid & 1;         // cols wn*32..+31
    const int g   = lane >> 2;
    const int tig = lane & 3;

    const __half* Eg = g_E + ((size_t)bh * SQ + i0) * SQ;
    float* Ag32 = attn + ((size_t)bh * SQ + i0) * SQ;
    const __half* Vth = g_Vth + (size_t)bh * DH * SQ;

    const int rg = (t >> 3) * 4;     // rows rg..rg+3
    const int kg = (t & 7) * 8;      // k cols kg..kg+7

    uint4 ra[4];
    float fv[4];

    float acc[2][4][4];
    #pragma unroll
    for (int a = 0; a < 2; ++a)
        #pragma unroll
        for (int b = 0; b < 4; ++b)
            #pragma unroll
            for (int c = 0; c < 4; ++c) acc[a][b][c] = 0.0f;

    auto ldF = [&](int kt) {
        #pragma unroll
        for (int i = 0; i < 4; ++i)
            fv[i] = g_F[((size_t)bh * SQ + i0 + rg + i) * NTILE + kt];
    };
    auto ldA = [&](int n) {
        #pragma unroll
        for (int i = 0; i < 4; ++i)
            ra[i] = *(const uint4*)(Eg + (size_t)(rg + i) * SQ + n * AV_BK + kg);
    };
    auto ldV = [&](int n, int buf) {
        #pragma unroll
        for (int it = 0; it < 2; ++it) {
            const int id  = it * 256 + t;
            const int d   = id >> 3;
            const int seg = (id & 7) * 8;
            cpasync16(VsH[buf] + d * AVP + seg, Vth + (size_t)d * SQ + n * AV_BK + seg);
        }
        cp_commit();
    };
    auto procA = [&](int n, int buf) {
        #pragma unroll
        for (int i = 0; i < 4; ++i) {
            const int row = rg + i;
            const float f = fv[i];
            const __half2* hp = (const __half2*)&ra[i];
            float2 p0 = __half22float2(hp[0]);
            float2 p1 = __half22float2(hp[1]);
            float2 p2 = __half22float2(hp[2]);
            float2 p3 = __half22float2(hp[3]);
            p0.x *= f; p0.y *= f; p1.x *= f; p1.y *= f;
            p2.x *= f; p2.y *= f; p3.x *= f; p3.y *= f;
            float* p = Ag32 + (size_t)row * SQ + n * AV_BK + kg;
            *(float4*)p       = make_float4(p0.x, p0.y, p1.x, p1.y);
            *(float4*)(p + 4) = make_float4(p2.x, p2.y, p3.x, p3.y);
            uint4 w;
            *(__half2*)&w.x = __float22half2_rn(p0);
            *(__half2*)&w.y = __float22half2_rn(p1);
            *(__half2*)&w.z = __float22half2_rn(p2);
            *(__half2*)&w.w = __float22half2_rn(p3);
            *(uint4*)&As[buf][row * AVP + kg] = w;
        }
    };

    ldF(0);
    ldA(0);
    ldV(0, 0);
    procA(0, 0);
    cp_wait0();
    __syncthreads();

    for (int c = 0; c < SQ / AV_BK; ++c) {
        const int cur = c & 1;
        if (c < SQ / AV_BK - 1) {
            const int n = c + 1;
            if ((n & 1) == 0) ldF(n >> 1);
            ldA(n);
            ldV(n, 1 - cur);
        }
        {
            const unsigned* A  = (const unsigned*)As[cur];
            const unsigned* VH = (const unsigned*)VsH[cur];
            #pragma unroll
            for (int ks = 0; ks < 4; ++ks) {
                unsigned a[2][4];
                #pragma unroll
                for (int mi = 0; mi < 2; ++mi) {
                    const int w = (wm * 32 + mi * 16 + g) * AVPW + 8 * ks + tig;
                    a[mi][0] = A[w];       a[mi][1] = A[w + 8 * AVPW];
                    a[mi][2] = A[w + 4];   a[mi][3] = A[w + 8 * AVPW + 4];
                }
                #pragma unroll
                for (int ni = 0; ni < 4; ++ni) {
                    const int wb = (wn * 32 + ni * 8 + g) * AVPW + 8 * ks + tig;
                    const unsigned bh0 = VH[wb], bh1 = VH[wb + 4];
                    MMA_F16(acc[0][ni], a[0], bh0, bh1);
                    MMA_F16(acc[1][ni], a[1], bh0, bh1);
                }
            }
        }
        if (c < SQ / AV_BK - 1) {
            procA(c + 1, 1 - cur);
            cp_wait0();
        }
        __syncthreads();
    }

    #pragma unroll
    for (int mi = 0; mi < 2; ++mi)
        #pragma unroll
        for (int ni = 0; ni < 4; ++ni)
            #pragma unroll
            for (int h = 0; h < 2; ++h) {
                const int row = i0 + wm * 32 + mi * 16 + h * 8 + g;
                const int col = wn * 32 + ni * 8 + 2 * tig;
                *(float2*)(ctx + ((size_t)bh * SQ + row) * DH + col) =
                    make_float2(acc[mi][ni][2 * h], acc[mi][ni][2 * h + 1]);
            }
}

// =====================================================================
extern "C" void kernel_launch(void* const* d_in, const int* in_sizes, int n_in,
                              void* d_out, int out_size) {
    const float* q = (const float*)d_in[0];
    const float* k = (const float*)d_in[1];
    const float* v = (const float*)d_in[2];
    const void*  mask = d_in[3];

    float* ctx  = (float*)d_out;                              // [24, 2048, 64]
    float* attn = (float*)d_out + (size_t)NBH * SQ * DH;      // [24, 2048, 2048]

    const int qk_smem = 4 * 128 * QP * 2 + 512 * 4;           // 75776
    cudaFuncSetAttribute(qk_scores_kernel,
                         cudaFuncAttributeMaxDynamicSharedMemorySize, qk_smem);
    const int av_smem = (2 * 128 * AVP + 2 * 64 * AVP) * 2;   // 55296
    cudaFuncSetAttribute(av_kernel,
                         cudaFuncAttributeMaxDynamicSharedMemorySize, av_smem);

    dim3 gv(SQ / 64, NBH);
    vconv_kernel<<<gv, 256>>>(v, (const unsigned char*)mask);

    dim3 g1(SQ / 128, SQ / 128, NBH);
    qk_scores_kernel<<<g1, 256, qk_smem>>>(q, k, mask);

    combine_kernel<<<NBH * SQ / 128, 128>>>();

    dim3 g3(SQ / 128, NBH);
    av_kernel<<<g3, 256, av_smem>>>(attn, ctx);
}